// round 5
// baseline (speedup 1.0000x reference)
#include <cuda_runtime.h>
#include <math.h>
#include <stdint.h>

// Problem constants
#define B 16
#define S 2048
#define M 4
#define E 128
#define HH 128
#define VOCAB 100000
#define NE 4000
#define NR 200
#define FULLMASK 0xffffffffu

// ---------------- device scratch (no allocation allowed) ----------------
__device__ float g_h[B * HH];
__device__ float g_u[B * HH];
__device__ float g_logit[B * S];
__device__ float g_emb1[(size_t)B * S * E];   // summed C1 embeddings
__device__ float g_emb2[(size_t)B * S * E];   // summed C2 embeddings

// ---------------- threefry2x32-20 (JAX) ----------------
__host__ __device__ __forceinline__ uint32_t rotl32(uint32_t v, int d) {
    return (v << d) | (v >> (32 - d));
}

__host__ __device__ __forceinline__ void threefry2x32(
    uint32_t k0, uint32_t k1, uint32_t x0, uint32_t x1,
    uint32_t& o0, uint32_t& o1)
{
    uint32_t ks0 = k0, ks1 = k1;
    uint32_t ks2 = k0 ^ k1 ^ 0x1BD11BDAu;
    x0 += ks0; x1 += ks1;
    const int rA[4] = {13, 15, 26, 6};
    const int rB[4] = {17, 29, 16, 24};
    #pragma unroll
    for (int i = 0; i < 4; i++) { x0 += x1; x1 = rotl32(x1, rA[i]); x1 ^= x0; }
    x0 += ks1; x1 += ks2 + 1u;
    #pragma unroll
    for (int i = 0; i < 4; i++) { x0 += x1; x1 = rotl32(x1, rB[i]); x1 ^= x0; }
    x0 += ks2; x1 += ks0 + 2u;
    #pragma unroll
    for (int i = 0; i < 4; i++) { x0 += x1; x1 = rotl32(x1, rA[i]); x1 ^= x0; }
    x0 += ks0; x1 += ks1 + 3u;
    #pragma unroll
    for (int i = 0; i < 4; i++) { x0 += x1; x1 = rotl32(x1, rB[i]); x1 ^= x0; }
    x0 += ks1; x1 += ks2 + 4u;
    #pragma unroll
    for (int i = 0; i < 4; i++) { x0 += x1; x1 = rotl32(x1, rA[i]); x1 ^= x0; }
    x0 += ks2; x1 += ks0 + 5u;
    o0 = x0; o1 = x1;
}

// ---------------- h = hidden @ Wm^T + Wb ; u = h ----------------
__global__ void k_h(const float* __restrict__ hidden,
                    const float* __restrict__ Wm,
                    const float* __restrict__ Wb)
{
    int b = blockIdx.x, t = threadIdx.x;
    __shared__ float sh[HH];
    sh[t] = hidden[b * HH + t];
    __syncthreads();
    float acc = Wb[t];
    const float* w = Wm + (size_t)t * HH;
    #pragma unroll 8
    for (int k = 0; k < HH; k++) acc = fmaf(w[k], sh[k], acc);
    g_h[b * HH + t] = acc;
    g_u[b * HH + t] = acc;
}

// ---------------- all three head GEMVs: warp per output column n ----------------
__global__ void k_head_all(const float* __restrict__ W1w, const float* __restrict__ W1b,
                           const float* __restrict__ W3w, const float* __restrict__ W3b,
                           const float* __restrict__ W4w, const float* __restrict__ W4b,
                           float* __restrict__ o_sp, float* __restrict__ o_qh,
                           float* __restrict__ o_qt)
{
    int gid  = blockIdx.x * blockDim.x + threadIdx.x;
    int w    = gid >> 5, lane = gid & 31;
    if (w >= 2 + NE + NR) return;
    const float *W, *bias; float* outl; int N, n;
    if (w < 2)            { W = W1w; bias = W1b; outl = o_sp; N = 2;  n = w; }
    else if (w < 2 + NE)  { W = W3w; bias = W3b; outl = o_qh; N = NE; n = w - 2; }
    else                  { W = W4w; bias = W4b; outl = o_qt; N = NR; n = w - 2 - NE; }

    float4 w4 = __ldg((const float4*)(W + (size_t)n * HH) + lane);
    float  bs = __ldg(bias + n);
    #pragma unroll
    for (int b = 0; b < B; b++) {
        float4 h4 = *((const float4*)(g_h + b * HH) + lane);
        float s = w4.x * h4.x + w4.y * h4.y + w4.z * h4.z + w4.w * h4.w;
        #pragma unroll
        for (int o = 16; o; o >>= 1) s += __shfl_down_sync(FULLMASK, s, o);
        if (lane == 0) outl[b * N + n] = s + bs;
    }
}

// ---------------- gumbel noise + argmax + one-hot, one block per (b, head) ----------------
__global__ void k_argmax_all(const float* __restrict__ o_sp, const float* __restrict__ o_qh,
                             const float* __restrict__ o_qt,
                             float* __restrict__ a_sp, float* __restrict__ a_qh,
                             float* __restrict__ a_qt,
                             uint32_t k1a, uint32_t k1b, uint32_t k2a, uint32_t k2b,
                             uint32_t k3a, uint32_t k3b)
{
    int b = blockIdx.x, head = blockIdx.y, t = threadIdx.x;
    const float* L; float* A; int N; uint32_t ka, kb;
    if (head == 0)      { L = o_sp; A = a_sp; N = 2;  ka = k1a; kb = k1b; }
    else if (head == 1) { L = o_qh; A = a_qh; N = NE; ka = k2a; kb = k2b; }
    else                { L = o_qt; A = a_qt; N = NR; ka = k3a; kb = k3b; }

    float bv = -INFINITY; int bi = 0x7fffffff;
    for (int i = t; i < N; i += 256) {
        int idx = b * N + i;
        float logit = __ldg(L + idx);
        uint32_t o0, o1;
        threefry2x32(ka, kb, 0u, (uint32_t)idx, o0, o1);
        uint32_t bits = o0 ^ o1;
        float u = __uint_as_float((bits >> 9) | 0x3F800000u) - 1.0f;
        float v = fmaxf(1e-10f, u + 1e-10f);
        float g = -logf(-logf(v));
        float nv = logit + g;
        if (nv > bv || (nv == bv && i < bi)) { bv = nv; bi = i; }
    }
    __shared__ float sv[256];
    __shared__ int   si[256];
    sv[t] = bv; si[t] = bi;
    __syncthreads();
    for (int o = 128; o; o >>= 1) {
        if (t < o) {
            if (sv[t + o] > sv[t] || (sv[t + o] == sv[t] && si[t + o] < si[t])) {
                sv[t] = sv[t + o]; si[t] = si[t + o];
            }
        }
        __syncthreads();
    }
    int best = si[0];
    float* out = A + b * N;
    for (int i = t; i < N; i += 256) out[i] = (i == best) ? 1.0f : 0.0f;
}

// ---------------- hop-0 logit: gather C0 rows, dot with u (2 slots/warp) ------
__global__ void k_hop_logit(const int* __restrict__ story,
                            const float* __restrict__ Ct)
{
    int gid  = blockIdx.x * blockDim.x + threadIdx.x;
    int warp = gid >> 5, lane = gid & 31;
    if (warp >= B * S / 2) return;
    int s0 = warp * 2;
    int b  = s0 >> 11;
    int4 ia = __ldg((const int4*)story + s0);
    int4 ib = __ldg((const int4*)story + s0 + 1);
    float4 a0 = __ldg((const float4*)(Ct + (size_t)ia.x * E) + lane);
    float4 a1 = __ldg((const float4*)(Ct + (size_t)ia.y * E) + lane);
    float4 a2 = __ldg((const float4*)(Ct + (size_t)ia.z * E) + lane);
    float4 a3 = __ldg((const float4*)(Ct + (size_t)ia.w * E) + lane);
    float4 b0 = __ldg((const float4*)(Ct + (size_t)ib.x * E) + lane);
    float4 b1 = __ldg((const float4*)(Ct + (size_t)ib.y * E) + lane);
    float4 b2 = __ldg((const float4*)(Ct + (size_t)ib.z * E) + lane);
    float4 b3 = __ldg((const float4*)(Ct + (size_t)ib.w * E) + lane);
    float4 u4 = *((const float4*)(g_u + b * HH) + lane);
    float sa = (a0.x + a1.x + a2.x + a3.x) * u4.x
             + (a0.y + a1.y + a2.y + a3.y) * u4.y
             + (a0.z + a1.z + a2.z + a3.z) * u4.z
             + (a0.w + a1.w + a2.w + a3.w) * u4.w;
    float sb = (b0.x + b1.x + b2.x + b3.x) * u4.x
             + (b0.y + b1.y + b2.y + b3.y) * u4.y
             + (b0.z + b1.z + b2.z + b3.z) * u4.z
             + (b0.w + b1.w + b2.w + b3.w) * u4.w;
    #pragma unroll
    for (int o = 16; o; o >>= 1) {
        sa += __shfl_down_sync(FULLMASK, sa, o);
        sb += __shfl_down_sync(FULLMASK, sb, o);
    }
    if (lane == 0) { g_logit[s0] = sa; g_logit[s0 + 1] = sb; }
}

// ---------------- fused softmax + u update + emb materialization ----------------
// 1024 blocks (64 per batch), 256 threads = 8 warps, 32 slots per block,
// 4 slots per warp. Block-redundant softmax stats, warp-per-slot float4 gathers,
// per-slot summed embedding written to scratch, smem reduce + atomicAdd into g_u.
__global__ void k_update(const int* __restrict__ story,
                         const float* __restrict__ Ct,
                         float* __restrict__ emb_out)
{
    int blk = blockIdx.x;
    int b   = blk >> 6;                 // 64 blocks per batch
    int slot0 = (blk & 63) * 32;
    int t = threadIdx.x, lane = t & 31, w = t >> 5;

    // softmax stats over the full row (scalars only)
    const float* l = g_logit + b * S;
    __shared__ float red[256];
    float m = -INFINITY;
    for (int i = t; i < S; i += 256) m = fmaxf(m, __ldg(l + i));
    red[t] = m; __syncthreads();
    #pragma unroll
    for (int o = 128; o; o >>= 1) { if (t < o) red[t] = fmaxf(red[t], red[t + o]); __syncthreads(); }
    m = red[0]; __syncthreads();
    float sum = 0.f;
    for (int i = t; i < S; i += 256) sum += expf(__ldg(l + i) - m);
    red[t] = sum; __syncthreads();
    #pragma unroll
    for (int o = 128; o; o >>= 1) { if (t < o) red[t] += red[t + o]; __syncthreads(); }
    float inv = 1.0f / red[0];
    __syncthreads();

    // gather: warp w handles slots [slot0 + w*4, +4), 2 per iteration
    float4 acc = make_float4(0.f, 0.f, 0.f, 0.f);
    int sbase = b * S + slot0 + w * 4;
    #pragma unroll
    for (int i = 0; i < 4; i += 2) {
        int s0 = sbase + i, s1 = s0 + 1;
        int4 i0 = __ldg((const int4*)story + s0);
        int4 i1 = __ldg((const int4*)story + s1);
        float p0 = expf(__ldg(g_logit + s0) - m) * inv;
        float p1 = expf(__ldg(g_logit + s1) - m) * inv;
        float4 a0 = __ldg((const float4*)(Ct + (size_t)i0.x * E) + lane);
        float4 a1 = __ldg((const float4*)(Ct + (size_t)i0.y * E) + lane);
        float4 a2 = __ldg((const float4*)(Ct + (size_t)i0.z * E) + lane);
        float4 a3 = __ldg((const float4*)(Ct + (size_t)i0.w * E) + lane);
        float4 c0 = __ldg((const float4*)(Ct + (size_t)i1.x * E) + lane);
        float4 c1 = __ldg((const float4*)(Ct + (size_t)i1.y * E) + lane);
        float4 c2 = __ldg((const float4*)(Ct + (size_t)i1.z * E) + lane);
        float4 c3 = __ldg((const float4*)(Ct + (size_t)i1.w * E) + lane);
        float4 v0 = make_float4(a0.x + a1.x + a2.x + a3.x,
                                a0.y + a1.y + a2.y + a3.y,
                                a0.z + a1.z + a2.z + a3.z,
                                a0.w + a1.w + a2.w + a3.w);
        float4 v1 = make_float4(c0.x + c1.x + c2.x + c3.x,
                                c0.y + c1.y + c2.y + c3.y,
                                c0.z + c1.z + c2.z + c3.z,
                                c0.w + c1.w + c2.w + c3.w);
        *((float4*)(emb_out + (size_t)s0 * E) + lane) = v0;
        *((float4*)(emb_out + (size_t)s1 * E) + lane) = v1;
        acc.x = fmaf(p0, v0.x, acc.x); acc.y = fmaf(p0, v0.y, acc.y);
        acc.z = fmaf(p0, v0.z, acc.z); acc.w = fmaf(p0, v0.w, acc.w);
        acc.x = fmaf(p1, v1.x, acc.x); acc.y = fmaf(p1, v1.y, acc.y);
        acc.z = fmaf(p1, v1.z, acc.z); acc.w = fmaf(p1, v1.w, acc.w);
    }

    // cross-warp reduce: 8 warps x 128 floats
    __shared__ float sred[8][128];
    *((float4*)&sred[w][lane * 4]) = acc;
    __syncthreads();
    if (t < 128) {
        float v = sred[0][t];
        #pragma unroll
        for (int ww = 1; ww < 8; ww++) v += sred[ww][t];
        atomicAdd(&g_u[b * HH + t], v);
    }
}

// ---------------- logit from precomputed emb (sequential read, 4 slots/warp) ----
__global__ void k_logit_seq(const float* __restrict__ emb)
{
    int gid  = blockIdx.x * blockDim.x + threadIdx.x;
    int warp = gid >> 5, lane = gid & 31;
    if (warp >= B * S / 4) return;
    int s0 = warp * 4;
    int b  = s0 >> 11;
    float4 e0 = __ldg((const float4*)(emb + (size_t)s0 * E) + lane);
    float4 e1 = __ldg((const float4*)(emb + (size_t)(s0 + 1) * E) + lane);
    float4 e2 = __ldg((const float4*)(emb + (size_t)(s0 + 2) * E) + lane);
    float4 e3 = __ldg((const float4*)(emb + (size_t)(s0 + 3) * E) + lane);
    float4 u4 = *((const float4*)(g_u + b * HH) + lane);
    float d0 = e0.x * u4.x + e0.y * u4.y + e0.z * u4.z + e0.w * u4.w;
    float d1 = e1.x * u4.x + e1.y * u4.y + e1.z * u4.z + e1.w * u4.w;
    float d2 = e2.x * u4.x + e2.y * u4.y + e2.z * u4.z + e2.w * u4.w;
    float d3 = e3.x * u4.x + e3.y * u4.y + e3.z * u4.z + e3.w * u4.w;
    #pragma unroll
    for (int o = 16; o; o >>= 1) {
        d0 += __shfl_down_sync(FULLMASK, d0, o);
        d1 += __shfl_down_sync(FULLMASK, d1, o);
        d2 += __shfl_down_sync(FULLMASK, d2, o);
        d3 += __shfl_down_sync(FULLMASK, d3, o);
    }
    if (lane == 0) {
        g_logit[s0] = d0; g_logit[s0 + 1] = d1;
        g_logit[s0 + 2] = d2; g_logit[s0 + 3] = d3;
    }
}

// ---------------- final: logit from emb2, sigmoid + length mask -> out ----------
__global__ void k_logit_mask_seq(const float* __restrict__ emb,
                                 const int* __restrict__ lengths,
                                 float* __restrict__ out)
{
    int gid  = blockIdx.x * blockDim.x + threadIdx.x;
    int warp = gid >> 5, lane = gid & 31;
    if (warp >= B * S / 4) return;
    int s0 = warp * 4;
    int b  = s0 >> 11;
    float4 e0 = __ldg((const float4*)(emb + (size_t)s0 * E) + lane);
    float4 e1 = __ldg((const float4*)(emb + (size_t)(s0 + 1) * E) + lane);
    float4 e2 = __ldg((const float4*)(emb + (size_t)(s0 + 2) * E) + lane);
    float4 e3 = __ldg((const float4*)(emb + (size_t)(s0 + 3) * E) + lane);
    float4 u4 = *((const float4*)(g_u + b * HH) + lane);
    float d0 = e0.x * u4.x + e0.y * u4.y + e0.z * u4.z + e0.w * u4.w;
    float d1 = e1.x * u4.x + e1.y * u4.y + e1.z * u4.z + e1.w * u4.w;
    float d2 = e2.x * u4.x + e2.y * u4.y + e2.z * u4.z + e2.w * u4.w;
    float d3 = e3.x * u4.x + e3.y * u4.y + e3.z * u4.z + e3.w * u4.w;
    #pragma unroll
    for (int o = 16; o; o >>= 1) {
        d0 += __shfl_down_sync(FULLMASK, d0, o);
        d1 += __shfl_down_sync(FULLMASK, d1, o);
        d2 += __shfl_down_sync(FULLMASK, d2, o);
        d3 += __shfl_down_sync(FULLMASK, d3, o);
    }
    if (lane == 0) {
        int len = __ldg(lengths + b);
        int sl = s0 & (S - 1);
        out[s0]     = (sl < len)     ? 1.0f / (1.0f + expf(-d0)) : 0.0f;
        out[s0 + 1] = (sl + 1 < len) ? 1.0f / (1.0f + expf(-d1)) : 0.0f;
        out[s0 + 2] = (sl + 2 < len) ? 1.0f / (1.0f + expf(-d2)) : 0.0f;
        out[s0 + 3] = (sl + 3 < len) ? 1.0f / (1.0f + expf(-d3)) : 0.0f;
    }
}

// ---------------- host launch ----------------
extern "C" void kernel_launch(void* const* d_in, const int* in_sizes, int n_in,
                              void* d_out, int out_size)
{
    const int*   story   = (const int*)d_in[0];
    const int*   lengths = (const int*)d_in[1];
    const float* hidden  = (const float*)d_in[2];
    // d_in[3] global_pointer: unused (is_decoding == 0 path)
    const float* C       = (const float*)d_in[4];
    const float* Wm      = (const float*)d_in[5];
    const float* Wb      = (const float*)d_in[6];
    const float* W1w     = (const float*)d_in[7];
    const float* W1b     = (const float*)d_in[8];
    const float* W3w     = (const float*)d_in[9];
    const float* W3b     = (const float*)d_in[10];
    const float* W4w     = (const float*)d_in[11];
    const float* W4b     = (const float*)d_in[12];

    float* out = (float*)d_out;
    float* o_sp   = out;                       // [B,2]
    float* o_spa  = out + B * 2;               // [B,2]
    float* o_qh   = out + B * 4;               // [B,4000]
    float* o_qha  = o_qh + B * NE;             // [B,4000]
    float* o_qt   = o_qha + B * NE;            // [B,200]
    float* o_qta  = o_qt + B * NR;             // [B,200]
    float* o_mask = o_qta + B * NR;            // [B,S]

    // JAX partitionable split of key(42): k_i = threefry(key, (0, i))
    uint32_t k1a, k1b, k2a, k2b, k3a, k3b;
    threefry2x32(0u, 42u, 0u, 0u, k1a, k1b);
    threefry2x32(0u, 42u, 0u, 1u, k2a, k2b);
    threefry2x32(0u, 42u, 0u, 2u, k3a, k3b);

    const size_t TBL = (size_t)VOCAB * E;

    // side stream + events, created once on the (non-captured) correctness call
    static cudaStream_t s_side = 0;
    static cudaEvent_t ev_fork = 0, ev_join = 0;
    if (!s_side) {
        cudaStreamCreateWithFlags(&s_side, cudaStreamNonBlocking);
        cudaEventCreateWithFlags(&ev_fork, cudaEventDisableTiming);
        cudaEventCreateWithFlags(&ev_join, cudaEventDisableTiming);
    }

    k_h<<<B, HH>>>(hidden, Wm, Wb);

    // fork: heads run concurrently with the hop chain
    cudaEventRecord(ev_fork, 0);
    cudaStreamWaitEvent(s_side, ev_fork, 0);
    {
        int warps  = 2 + NE + NR;
        int blocks = (warps * 32 + 255) / 256;
        k_head_all<<<blocks, 256, 0, s_side>>>(W1w, W1b, W3w, W3b, W4w, W4b,
                                               o_sp, o_qh, o_qt);
        dim3 g(B, 3);
        k_argmax_all<<<g, 256, 0, s_side>>>(o_sp, o_qh, o_qt, o_spa, o_qha, o_qta,
                                            k1a, k1b, k2a, k2b, k3a, k3b);
    }
    cudaEventRecord(ev_join, s_side);

    // main hop chain
    int lblocks = (B * S / 2 * 32) / 256;
    k_hop_logit<<<lblocks, 256>>>(story, C);                    // hop0 logits (gather C0)
    k_update<<<1024, 256>>>(story, C + TBL, g_emb1);            // u += ..., emb1 = sum C1
    k_logit_seq<<<(B * S / 4 * 32) / 256, 256>>>(g_emb1);       // hop1 logits (stream emb1)
    k_update<<<1024, 256>>>(story, C + 2 * TBL, g_emb2);        // u += ..., emb2 = sum C2
    k_logit_mask_seq<<<(B * S / 4 * 32) / 256, 256>>>(g_emb2, lengths, o_mask);

    // join heads branch
    cudaStreamWaitEvent(0, ev_join, 0);
}

// round 6
// speedup vs baseline: 4.9048x; 4.9048x over previous
#include <cuda_runtime.h>
#include <math.h>
#include <stdint.h>

// Problem constants
#define B 16
#define S 2048
#define M 4
#define E 128
#define HH 128
#define VOCAB 100000
#define NE 4000
#define NR 200
#define FULLMASK 0xffffffffu

// ---------------- device scratch (no allocation allowed) ----------------
__device__ float g_h[B * HH];
__device__ float g_u[B * HH];
__device__ float g_logit[B * S];

// ---------------- threefry2x32-20 (JAX) ----------------
__host__ __device__ __forceinline__ uint32_t rotl32(uint32_t v, int d) {
    return (v << d) | (v >> (32 - d));
}

__host__ __device__ __forceinline__ void threefry2x32(
    uint32_t k0, uint32_t k1, uint32_t x0, uint32_t x1,
    uint32_t& o0, uint32_t& o1)
{
    uint32_t ks0 = k0, ks1 = k1;
    uint32_t ks2 = k0 ^ k1 ^ 0x1BD11BDAu;
    x0 += ks0; x1 += ks1;
    const int rA[4] = {13, 15, 26, 6};
    const int rB[4] = {17, 29, 16, 24};
    #pragma unroll
    for (int i = 0; i < 4; i++) { x0 += x1; x1 = rotl32(x1, rA[i]); x1 ^= x0; }
    x0 += ks1; x1 += ks2 + 1u;
    #pragma unroll
    for (int i = 0; i < 4; i++) { x0 += x1; x1 = rotl32(x1, rB[i]); x1 ^= x0; }
    x0 += ks2; x1 += ks0 + 2u;
    #pragma unroll
    for (int i = 0; i < 4; i++) { x0 += x1; x1 = rotl32(x1, rA[i]); x1 ^= x0; }
    x0 += ks0; x1 += ks1 + 3u;
    #pragma unroll
    for (int i = 0; i < 4; i++) { x0 += x1; x1 = rotl32(x1, rB[i]); x1 ^= x0; }
    x0 += ks1; x1 += ks2 + 4u;
    #pragma unroll
    for (int i = 0; i < 4; i++) { x0 += x1; x1 = rotl32(x1, rA[i]); x1 ^= x0; }
    x0 += ks2; x1 += ks0 + 5u;
    o0 = x0; o1 = x1;
}

// ---------------- h = hidden @ Wm^T + Wb ; u = h ----------------
__global__ void k_h(const float* __restrict__ hidden,
                    const float* __restrict__ Wm,
                    const float* __restrict__ Wb)
{
    int b = blockIdx.x, t = threadIdx.x;
    __shared__ float sh[HH];
    sh[t] = hidden[b * HH + t];
    __syncthreads();
    float acc = Wb[t];
    const float* w = Wm + (size_t)t * HH;
    #pragma unroll 8
    for (int k = 0; k < HH; k++) acc = fmaf(w[k], sh[k], acc);
    g_h[b * HH + t] = acc;
    g_u[b * HH + t] = acc;
}

// ============ K1: fused hop-0 logit gather  +  three head GEMVs ============
// blocks [0, LB): hop0 logits (2 slots/warp, identical to proven k_hop_logit)
// blocks [LB, LB+HB): head GEMVs (warp per output column, identical to k_head_all)
#define LB (B * S / 2 * 32 / 256)        // 2048
#define HEADW (2 + NE + NR)              // 4202 warps
#define HB ((HEADW * 32 + 255) / 256)    // 526

__global__ void k_fused1(const int* __restrict__ story,
                         const float* __restrict__ C0,
                         const float* __restrict__ W1w, const float* __restrict__ W1b,
                         const float* __restrict__ W3w, const float* __restrict__ W3b,
                         const float* __restrict__ W4w, const float* __restrict__ W4b,
                         float* __restrict__ o_sp, float* __restrict__ o_qh,
                         float* __restrict__ o_qt)
{
    if (blockIdx.x < LB) {
        // ---- hop0 logit part ----
        int gid  = blockIdx.x * blockDim.x + threadIdx.x;
        int warp = gid >> 5, lane = gid & 31;
        int s0 = warp * 2;
        int b  = s0 >> 11;
        int4 ia = __ldg((const int4*)story + s0);
        int4 ib = __ldg((const int4*)story + s0 + 1);
        float4 a0 = __ldg((const float4*)(C0 + (size_t)ia.x * E) + lane);
        float4 a1 = __ldg((const float4*)(C0 + (size_t)ia.y * E) + lane);
        float4 a2 = __ldg((const float4*)(C0 + (size_t)ia.z * E) + lane);
        float4 a3 = __ldg((const float4*)(C0 + (size_t)ia.w * E) + lane);
        float4 b0 = __ldg((const float4*)(C0 + (size_t)ib.x * E) + lane);
        float4 b1 = __ldg((const float4*)(C0 + (size_t)ib.y * E) + lane);
        float4 b2 = __ldg((const float4*)(C0 + (size_t)ib.z * E) + lane);
        float4 b3 = __ldg((const float4*)(C0 + (size_t)ib.w * E) + lane);
        float4 u4 = *((const float4*)(g_u + b * HH) + lane);
        float sa = (a0.x + a1.x + a2.x + a3.x) * u4.x
                 + (a0.y + a1.y + a2.y + a3.y) * u4.y
                 + (a0.z + a1.z + a2.z + a3.z) * u4.z
                 + (a0.w + a1.w + a2.w + a3.w) * u4.w;
        float sb = (b0.x + b1.x + b2.x + b3.x) * u4.x
                 + (b0.y + b1.y + b2.y + b3.y) * u4.y
                 + (b0.z + b1.z + b2.z + b3.z) * u4.z
                 + (b0.w + b1.w + b2.w + b3.w) * u4.w;
        #pragma unroll
        for (int o = 16; o; o >>= 1) {
            sa += __shfl_down_sync(FULLMASK, sa, o);
            sb += __shfl_down_sync(FULLMASK, sb, o);
        }
        if (lane == 0) { g_logit[s0] = sa; g_logit[s0 + 1] = sb; }
    } else {
        // ---- head GEMV part ----
        int gid  = (blockIdx.x - LB) * blockDim.x + threadIdx.x;
        int w    = gid >> 5, lane = gid & 31;
        if (w >= HEADW) return;
        const float *W, *bias; float* outl; int N, n;
        if (w < 2)            { W = W1w; bias = W1b; outl = o_sp; N = 2;  n = w; }
        else if (w < 2 + NE)  { W = W3w; bias = W3b; outl = o_qh; N = NE; n = w - 2; }
        else                  { W = W4w; bias = W4b; outl = o_qt; N = NR; n = w - 2 - NE; }

        float4 w4 = __ldg((const float4*)(W + (size_t)n * HH) + lane);
        float  bs = __ldg(bias + n);
        #pragma unroll
        for (int b = 0; b < B; b++) {
            float4 h4 = *((const float4*)(g_h + b * HH) + lane);
            float s = w4.x * h4.x + w4.y * h4.y + w4.z * h4.z + w4.w * h4.w;
            #pragma unroll
            for (int o = 16; o; o >>= 1) s += __shfl_down_sync(FULLMASK, s, o);
            if (lane == 0) outl[b * N + n] = s + bs;
        }
    }
}

// ============ K2: fused softmax+u-update (C1)  +  gumbel argmax one-hot ============
// blocks [0, 256): update part (identical to proven R4 k_update)
// blocks [256, 304): argmax part: blk2 = blockIdx-256, head = blk2/16, b = blk2%16
__device__ __forceinline__ void update_body(const int* __restrict__ story,
                                            const float* __restrict__ Ct,
                                            int blk)
{
    int b   = blk >> 4;                 // 16 blocks per batch
    int slot0 = (blk & 15) * 128;
    int t = threadIdx.x, lane = t & 31, w = t >> 5;

    const float* l = g_logit + b * S;
    __shared__ float red[256];
    float m = -INFINITY;
    for (int i = t; i < S; i += 256) m = fmaxf(m, __ldg(l + i));
    red[t] = m; __syncthreads();
    #pragma unroll
    for (int o = 128; o; o >>= 1) { if (t < o) red[t] = fmaxf(red[t], red[t + o]); __syncthreads(); }
    m = red[0]; __syncthreads();
    float sum = 0.f;
    for (int i = t; i < S; i += 256) sum += expf(__ldg(l + i) - m);
    red[t] = sum; __syncthreads();
    #pragma unroll
    for (int o = 128; o; o >>= 1) { if (t < o) red[t] += red[t + o]; __syncthreads(); }
    float inv = 1.0f / red[0];
    __syncthreads();

    float4 acc = make_float4(0.f, 0.f, 0.f, 0.f);
    int sbase = b * S + slot0 + w * 16;
    #pragma unroll 1
    for (int i = 0; i < 16; i += 2) {
        int s0 = sbase + i, s1 = s0 + 1;
        int4 i0 = __ldg((const int4*)story + s0);
        int4 i1 = __ldg((const int4*)story + s1);
        float p0 = expf(__ldg(g_logit + s0) - m) * inv;
        float p1 = expf(__ldg(g_logit + s1) - m) * inv;
        float4 a0 = __ldg((const float4*)(Ct + (size_t)i0.x * E) + lane);
        float4 a1 = __ldg((const float4*)(Ct + (size_t)i0.y * E) + lane);
        float4 a2 = __ldg((const float4*)(Ct + (size_t)i0.z * E) + lane);
        float4 a3 = __ldg((const float4*)(Ct + (size_t)i0.w * E) + lane);
        float4 c0 = __ldg((const float4*)(Ct + (size_t)i1.x * E) + lane);
        float4 c1 = __ldg((const float4*)(Ct + (size_t)i1.y * E) + lane);
        float4 c2 = __ldg((const float4*)(Ct + (size_t)i1.z * E) + lane);
        float4 c3 = __ldg((const float4*)(Ct + (size_t)i1.w * E) + lane);
        acc.x = fmaf(p0, a0.x + a1.x + a2.x + a3.x, acc.x);
        acc.y = fmaf(p0, a0.y + a1.y + a2.y + a3.y, acc.y);
        acc.z = fmaf(p0, a0.z + a1.z + a2.z + a3.z, acc.z);
        acc.w = fmaf(p0, a0.w + a1.w + a2.w + a3.w, acc.w);
        acc.x = fmaf(p1, c0.x + c1.x + c2.x + c3.x, acc.x);
        acc.y = fmaf(p1, c0.y + c1.y + c2.y + c3.y, acc.y);
        acc.z = fmaf(p1, c0.z + c1.z + c2.z + c3.z, acc.z);
        acc.w = fmaf(p1, c0.w + c1.w + c2.w + c3.w, acc.w);
    }

    __shared__ float sred[8][128];
    *((float4*)&sred[w][lane * 4]) = acc;
    __syncthreads();
    if (t < 128) {
        float v = sred[0][t];
        #pragma unroll
        for (int ww = 1; ww < 8; ww++) v += sred[ww][t];
        atomicAdd(&g_u[b * HH + t], v);
    }
}

__device__ __forceinline__ void argmax_body(const float* __restrict__ o_sp,
                                            const float* __restrict__ o_qh,
                                            const float* __restrict__ o_qt,
                                            float* __restrict__ a_sp,
                                            float* __restrict__ a_qh,
                                            float* __restrict__ a_qt,
                                            uint32_t k1a, uint32_t k1b,
                                            uint32_t k2a, uint32_t k2b,
                                            uint32_t k3a, uint32_t k3b,
                                            int blk2)
{
    int head = blk2 >> 4, b = blk2 & 15, t = threadIdx.x;
    const float* L; float* A; int N; uint32_t ka, kb;
    if (head == 0)      { L = o_sp; A = a_sp; N = 2;  ka = k1a; kb = k1b; }
    else if (head == 1) { L = o_qh; A = a_qh; N = NE; ka = k2a; kb = k2b; }
    else                { L = o_qt; A = a_qt; N = NR; ka = k3a; kb = k3b; }

    float bv = -INFINITY; int bi = 0x7fffffff;
    for (int i = t; i < N; i += 256) {
        int idx = b * N + i;
        float logit = __ldg(L + idx);
        uint32_t o0, o1;
        threefry2x32(ka, kb, 0u, (uint32_t)idx, o0, o1);
        uint32_t bits = o0 ^ o1;
        float u = __uint_as_float((bits >> 9) | 0x3F800000u) - 1.0f;
        float v = fmaxf(1e-10f, u + 1e-10f);
        float g = -logf(-logf(v));
        float nv = logit + g;
        if (nv > bv || (nv == bv && i < bi)) { bv = nv; bi = i; }
    }
    __shared__ float sv[256];
    __shared__ int   si[256];
    sv[t] = bv; si[t] = bi;
    __syncthreads();
    for (int o = 128; o; o >>= 1) {
        if (t < o) {
            if (sv[t + o] > sv[t] || (sv[t + o] == sv[t] && si[t + o] < si[t])) {
                sv[t] = sv[t + o]; si[t] = si[t + o];
            }
        }
        __syncthreads();
    }
    int best = si[0];
    float* out = A + b * N;
    for (int i = t; i < N; i += 256) out[i] = (i == best) ? 1.0f : 0.0f;
}

__global__ void k_fused2(const int* __restrict__ story,
                         const float* __restrict__ C1,
                         const float* __restrict__ o_sp, const float* __restrict__ o_qh,
                         const float* __restrict__ o_qt,
                         float* __restrict__ a_sp, float* __restrict__ a_qh,
                         float* __restrict__ a_qt,
                         uint32_t k1a, uint32_t k1b, uint32_t k2a, uint32_t k2b,
                         uint32_t k3a, uint32_t k3b)
{
    if (blockIdx.x < 256) {
        update_body(story, C1, blockIdx.x);
    } else {
        argmax_body(o_sp, o_qh, o_qt, a_sp, a_qh, a_qt,
                    k1a, k1b, k2a, k2b, k3a, k3b, blockIdx.x - 256);
    }
}

// plain update for hop 1 -> u (no argmax piggyback)
__global__ void k_update(const int* __restrict__ story,
                         const float* __restrict__ Ct)
{
    update_body(story, Ct, blockIdx.x);
}

// ---------------- hop logit (gather), 2 slots/warp ----------------
__global__ void k_hop_logit(const int* __restrict__ story,
                            const float* __restrict__ Ct)
{
    int gid  = blockIdx.x * blockDim.x + threadIdx.x;
    int warp = gid >> 5, lane = gid & 31;
    if (warp >= B * S / 2) return;
    int s0 = warp * 2;
    int b  = s0 >> 11;
    int4 ia = __ldg((const int4*)story + s0);
    int4 ib = __ldg((const int4*)story + s0 + 1);
    float4 a0 = __ldg((const float4*)(Ct + (size_t)ia.x * E) + lane);
    float4 a1 = __ldg((const float4*)(Ct + (size_t)ia.y * E) + lane);
    float4 a2 = __ldg((const float4*)(Ct + (size_t)ia.z * E) + lane);
    float4 a3 = __ldg((const float4*)(Ct + (size_t)ia.w * E) + lane);
    float4 b0 = __ldg((const float4*)(Ct + (size_t)ib.x * E) + lane);
    float4 b1 = __ldg((const float4*)(Ct + (size_t)ib.y * E) + lane);
    float4 b2 = __ldg((const float4*)(Ct + (size_t)ib.z * E) + lane);
    float4 b3 = __ldg((const float4*)(Ct + (size_t)ib.w * E) + lane);
    float4 u4 = *((const float4*)(g_u + b * HH) + lane);
    float sa = (a0.x + a1.x + a2.x + a3.x) * u4.x
             + (a0.y + a1.y + a2.y + a3.y) * u4.y
             + (a0.z + a1.z + a2.z + a3.z) * u4.z
             + (a0.w + a1.w + a2.w + a3.w) * u4.w;
    float sb = (b0.x + b1.x + b2.x + b3.x) * u4.x
             + (b0.y + b1.y + b2.y + b3.y) * u4.y
             + (b0.z + b1.z + b2.z + b3.z) * u4.z
             + (b0.w + b1.w + b2.w + b3.w) * u4.w;
    #pragma unroll
    for (int o = 16; o; o >>= 1) {
        sa += __shfl_down_sync(FULLMASK, sa, o);
        sb += __shfl_down_sync(FULLMASK, sb, o);
    }
    if (lane == 0) { g_logit[s0] = sa; g_logit[s0 + 1] = sb; }
}

// ---------------- final hop: gather logits -> sigmoid + length mask ----------------
__global__ void k_hop_logit_mask(const int* __restrict__ story,
                                 const float* __restrict__ Ct,
                                 const int* __restrict__ lengths,
                                 float* __restrict__ out)
{
    int gid  = blockIdx.x * blockDim.x + threadIdx.x;
    int warp = gid >> 5, lane = gid & 31;
    if (warp >= B * S / 2) return;
    int s0 = warp * 2;
    int b  = s0 >> 11;
    int4 ia = __ldg((const int4*)story + s0);
    int4 ib = __ldg((const int4*)story + s0 + 1);
    float4 a0 = __ldg((const float4*)(Ct + (size_t)ia.x * E) + lane);
    float4 a1 = __ldg((const float4*)(Ct + (size_t)ia.y * E) + lane);
    float4 a2 = __ldg((const float4*)(Ct + (size_t)ia.z * E) + lane);
    float4 a3 = __ldg((const float4*)(Ct + (size_t)ia.w * E) + lane);
    float4 b0 = __ldg((const float4*)(Ct + (size_t)ib.x * E) + lane);
    float4 b1 = __ldg((const float4*)(Ct + (size_t)ib.y * E) + lane);
    float4 b2 = __ldg((const float4*)(Ct + (size_t)ib.z * E) + lane);
    float4 b3 = __ldg((const float4*)(Ct + (size_t)ib.w * E) + lane);
    float4 u4 = *((const float4*)(g_u + b * HH) + lane);
    float sa = (a0.x + a1.x + a2.x + a3.x) * u4.x
             + (a0.y + a1.y + a2.y + a3.y) * u4.y
             + (a0.z + a1.z + a2.z + a3.z) * u4.z
             + (a0.w + a1.w + a2.w + a3.w) * u4.w;
    float sb = (b0.x + b1.x + b2.x + b3.x) * u4.x
             + (b0.y + b1.y + b2.y + b3.y) * u4.y
             + (b0.z + b1.z + b2.z + b3.z) * u4.z
             + (b0.w + b1.w + b2.w + b3.w) * u4.w;
    #pragma unroll
    for (int o = 16; o; o >>= 1) {
        sa += __shfl_down_sync(FULLMASK, sa, o);
        sb += __shfl_down_sync(FULLMASK, sb, o);
    }
    if (lane == 0) {
        int len = __ldg(lengths + b);
        int sl = s0 & (S - 1);
        out[s0]     = (sl < len)     ? 1.0f / (1.0f + expf(-sa)) : 0.0f;
        out[s0 + 1] = (sl + 1 < len) ? 1.0f / (1.0f + expf(-sb)) : 0.0f;
    }
}

// ---------------- host launch ----------------
extern "C" void kernel_launch(void* const* d_in, const int* in_sizes, int n_in,
                              void* d_out, int out_size)
{
    const int*   story   = (const int*)d_in[0];
    const int*   lengths = (const int*)d_in[1];
    const float* hidden  = (const float*)d_in[2];
    // d_in[3] global_pointer: unused (is_decoding == 0 path)
    const float* C       = (const float*)d_in[4];
    const float* Wm      = (const float*)d_in[5];
    const float* Wb      = (const float*)d_in[6];
    const float* W1w     = (const float*)d_in[7];
    const float* W1b     = (const float*)d_in[8];
    const float* W3w     = (const float*)d_in[9];
    const float* W3b     = (const float*)d_in[10];
    const float* W4w     = (const float*)d_in[11];
    const float* W4b     = (const float*)d_in[12];

    float* out = (float*)d_out;
    float* o_sp   = out;                       // [B,2]
    float* o_spa  = out + B * 2;               // [B,2]
    float* o_qh   = out + B * 4;               // [B,4000]
    float* o_qha  = o_qh + B * NE;             // [B,4000]
    float* o_qt   = o_qha + B * NE;            // [B,200]
    float* o_qta  = o_qt + B * NR;             // [B,200]
    float* o_mask = o_qta + B * NR;            // [B,S]

    // JAX partitionable split of key(42): k_i = threefry(key, (0, i))
    uint32_t k1a, k1b, k2a, k2b, k3a, k3b;
    threefry2x32(0u, 42u, 0u, 0u, k1a, k1b);
    threefry2x32(0u, 42u, 0u, 1u, k2a, k2b);
    threefry2x32(0u, 42u, 0u, 2u, k3a, k3b);

    const size_t TBL = (size_t)VOCAB * E;

    k_h<<<B, HH>>>(hidden, Wm, Wb);

    // K1: hop0 logit gather (C0) + all head GEMVs
    k_fused1<<<LB + HB, 256>>>(story, C,
                               W1w, W1b, W3w, W3b, W4w, W4b,
                               o_sp, o_qh, o_qt);

    // K2: softmax + u update (C1) + gumbel argmax one-hots
    k_fused2<<<256 + 48, 256>>>(story, C + TBL,
                                o_sp, o_qh, o_qt, o_spa, o_qha, o_qta,
                                k1a, k1b, k2a, k2b, k3a, k3b);

    // hop 1 logits (re-gather C1, L2-warm), update with C2
    int lblocks = (B * S / 2 * 32) / 256;
    k_hop_logit<<<lblocks, 256>>>(story, C + TBL);
    k_update<<<256, 256>>>(story, C + 2 * TBL);

    // hop 2 logits (re-gather C2, L2-warm) -> masked sigmoid
    k_hop_logit_mask<<<lblocks, 256>>>(story, C + 2 * TBL, lengths, o_mask);
}